// round 3
// baseline (speedup 1.0000x reference)
#include <cuda_runtime.h>
#include <cstdint>

#define BATCH 64
#define HDIM 512
#define HH 262144      // HDIM*HDIM
#define NSEQ 2048
#define NFOCUS 256

// ---------------- scratch (static device globals; no runtime allocation) ----
__device__ float g_Y[(size_t)BATCH * HH];      // 64 MB (Yq then Yk)
__device__ float g_Qp[8 * BATCH * HDIM];
__device__ float g_Q[BATCH * HDIM];
__device__ float g_w[BATCH * HDIM];
__device__ float g_compat[BATCH * NSEQ];
__device__ int   g_idx[BATCH * NFOCUS];

// ---------------- packed f32x2 helpers (Blackwell FFMA2 path) ---------------
__device__ __forceinline__ unsigned long long pack2(float lo, float hi) {
    unsigned long long r;
    asm("mov.b64 %0, {%1, %2};" : "=l"(r) : "f"(lo), "f"(hi));
    return r;
}
__device__ __forceinline__ void unpack2(unsigned long long v, float& lo, float& hi) {
    asm("mov.b64 {%0, %1}, %2;" : "=f"(lo), "=f"(hi) : "l"(v));
}
__device__ __forceinline__ void fma2(unsigned long long& d,
                                     unsigned long long a, unsigned long long b) {
    asm("fma.rn.f32x2 %0, %1, %2, %0;" : "+l"(d) : "l"(a), "l"(b));
}

// ---------------- Y = X @ W + bias   (64 x 262144, K=512) -------------------
__global__ __launch_bounds__(256, 2) void gemm_xw(
    const float* __restrict__ X, const float* __restrict__ W,
    const float* __restrict__ bias)
{
    __shared__ __align__(16) float Xs[2][16][66];
    __shared__ __align__(16) float Ws[2][16][256];
    const int n0  = blockIdx.x * 256;
    const int tid = threadIdx.x;
    const int tx  = tid & 31;   // n: tx*8
    const int ty  = tid >> 5;   // m: ty*8

    unsigned long long acc[4][8];
    #pragma unroll
    for (int mp = 0; mp < 4; mp++)
        #pragma unroll
        for (int n = 0; n < 8; n++) acc[mp][n] = 0ull;

    #pragma unroll
    for (int r = 0; r < 4; r++) {
        int e = tid + r * 256;
        Xs[0][e & 15][e >> 4] = X[(e >> 4) * HDIM + (e & 15)];
    }
    #pragma unroll
    for (int r = 0; r < 4; r++) {
        int e  = tid + r * 256;
        int kk = e >> 6, n4 = e & 63;
        *(float4*)&Ws[0][kk][n4 * 4] =
            *(const float4*)&W[(size_t)kk * HH + n0 + n4 * 4];
    }
    __syncthreads();

    for (int kc = 0; kc < 32; kc++) {
        const int cur = kc & 1, nxt = cur ^ 1;
        if (kc < 31) {
            const int k0 = (kc + 1) * 16;
            #pragma unroll
            for (int r = 0; r < 4; r++) {
                int e = tid + r * 256;
                Xs[nxt][e & 15][e >> 4] = X[(e >> 4) * HDIM + k0 + (e & 15)];
            }
            #pragma unroll
            for (int r = 0; r < 4; r++) {
                int e  = tid + r * 256;
                int kk = e >> 6, n4 = e & 63;
                *(float4*)&Ws[nxt][kk][n4 * 4] =
                    *(const float4*)&W[(size_t)(k0 + kk) * HH + n0 + n4 * 4];
            }
        }
        #pragma unroll
        for (int kk = 0; kk < 16; kk++) {
            unsigned long long ap[4];
            #pragma unroll
            for (int mp = 0; mp < 4; mp++)
                ap[mp] = *(const unsigned long long*)&Xs[cur][kk][ty * 8 + mp * 2];
            float4 b0 = *(const float4*)&Ws[cur][kk][tx * 8];
            float4 b1 = *(const float4*)&Ws[cur][kk][tx * 8 + 4];
            unsigned long long bp[8];
            bp[0] = pack2(b0.x, b0.x); bp[1] = pack2(b0.y, b0.y);
            bp[2] = pack2(b0.z, b0.z); bp[3] = pack2(b0.w, b0.w);
            bp[4] = pack2(b1.x, b1.x); bp[5] = pack2(b1.y, b1.y);
            bp[6] = pack2(b1.z, b1.z); bp[7] = pack2(b1.w, b1.w);
            #pragma unroll
            for (int mp = 0; mp < 4; mp++)
                #pragma unroll
                for (int n = 0; n < 8; n++)
                    fma2(acc[mp][n], ap[mp], bp[n]);
        }
        __syncthreads();
    }

    float bsv[8];
    #pragma unroll
    for (int n = 0; n < 8; n++) bsv[n] = bias[n0 + tx * 8 + n];
    #pragma unroll
    for (int mp = 0; mp < 4; mp++) {
        float o0[8], o1[8];
        #pragma unroll
        for (int n = 0; n < 8; n++) {
            float lo, hi;
            unpack2(acc[mp][n], lo, hi);
            o0[n] = lo + bsv[n];
            o1[n] = hi + bsv[n];
        }
        const int row0 = ty * 8 + mp * 2;
        size_t off0 = (size_t)row0 * HH + n0 + tx * 8;
        size_t off1 = off0 + HH;
        *(float4*)&g_Y[off0]     = make_float4(o0[0], o0[1], o0[2], o0[3]);
        *(float4*)&g_Y[off0 + 4] = make_float4(o0[4], o0[5], o0[6], o0[7]);
        *(float4*)&g_Y[off1]     = make_float4(o1[0], o1[1], o1[2], o1[3]);
        *(float4*)&g_Y[off1 + 4] = make_float4(o1[4], o1[5], o1[6], o1[7]);
    }
}

// ---------------- Qpart[s,b,k] = sum_{h in slice s} x[b,h] * Y[b, h*H + k] --
__global__ void contract_q(const float* __restrict__ X) {
    const int b = blockIdx.y, s = blockIdx.x;
    const int k = threadIdx.x;  // 512
    __shared__ float xs[64];
    if (k < 64) xs[k] = X[b * HDIM + s * 64 + k];
    __syncthreads();
    const float* Yb = g_Y + (size_t)b * HH + (size_t)s * 64 * HDIM + k;
    float a0 = 0.f, a1 = 0.f, a2 = 0.f, a3 = 0.f;
    #pragma unroll
    for (int hh = 0; hh < 64; hh += 4) {
        a0 = fmaf(xs[hh + 0], Yb[(hh + 0) * HDIM], a0);
        a1 = fmaf(xs[hh + 1], Yb[(hh + 1) * HDIM], a1);
        a2 = fmaf(xs[hh + 2], Yb[(hh + 2) * HDIM], a2);
        a3 = fmaf(xs[hh + 3], Yb[(hh + 3) * HDIM], a3);
    }
    g_Qp[(s * BATCH + b) * HDIM + k] = (a0 + a1) + (a2 + a3);
}

__global__ void reduce_q() {
    const int b = blockIdx.x, k = threadIdx.x;
    float v = 0.f;
    #pragma unroll
    for (int s = 0; s < 8; s++) v += g_Qp[(s * BATCH + b) * HDIM + k];
    g_Q[b * HDIM + k] = v;
}

// ---------------- w[b,h] = < Y[b, h*H : h*H+H] , Q[b,:] > -------------------
__global__ void contract_w() {
    const int b = blockIdx.y;
    const int warp = threadIdx.x >> 5, lane = threadIdx.x & 31;
    const int h = blockIdx.x * 8 + warp;
    __shared__ float qs[HDIM];
    for (int i = threadIdx.x; i < HDIM; i += 256) qs[i] = g_Q[b * HDIM + i];
    __syncthreads();
    const float* Yb = g_Y + (size_t)b * HH + (size_t)h * HDIM;
    float acc = 0.f;
    #pragma unroll
    for (int s2 = 0; s2 < 4; s2++) {
        const int i4 = lane + s2 * 32;
        float4 y = *(const float4*)&Yb[i4 * 4];
        float4 q = *(const float4*)&qs[i4 * 4];
        acc += y.x * q.x + y.y * q.y + y.z * q.z + y.w * q.w;
    }
    #pragma unroll
    for (int off = 16; off; off >>= 1) acc += __shfl_xor_sync(~0u, acc, off);
    if (lane == 0) g_w[b * HDIM + h] = acc;
}

// ---------------- compat[b,n] = norm * < ve[b,n,:], w[b,:] > ----------------
__global__ void compat_k(const float* __restrict__ ve) {
    const int b = blockIdx.y;
    const int warp = threadIdx.x >> 5, lane = threadIdx.x & 31;
    const int n = blockIdx.x * 8 + warp;
    __shared__ float ws[HDIM];
    for (int i = threadIdx.x; i < HDIM; i += 256) ws[i] = g_w[b * HDIM + i];
    __syncthreads();
    const float* v = ve + ((size_t)b * NSEQ + n) * HDIM;
    float acc = 0.f;
    #pragma unroll
    for (int s2 = 0; s2 < 4; s2++) {
        const int i4 = lane + s2 * 32;
        float4 y = *(const float4*)&v[i4 * 4];
        float4 q = *(const float4*)&ws[i4 * 4];
        acc += y.x * q.x + y.y * q.y + y.z * q.z + y.w * q.w;
    }
    #pragma unroll
    for (int off = 16; off; off >>= 1) acc += __shfl_xor_sync(~0u, acc, off);
    if (lane == 0) g_compat[b * NSEQ + n] = acc * 0.04419417382415922f;
}

// ---------------- per-batch ranking with fp32-exp flush boundary ------------
// score = softmax(compat) in fp32 with a fast exp that flushes/clamps below
// ln(2^-126) = -87.33654785. Above the boundary score is strictly monotone in
// compat -> rank by compat bits (desc). Below the boundary all scores tie ->
// rank by index (asc), matching stable argsort(-score).
__global__ __launch_bounds__(1024) void topk_k() {
    __shared__ unsigned sk[NSEQ];
    __shared__ int      si[NSEQ];
    __shared__ float    redf[32];
    const int b = blockIdx.x, t = threadIdx.x;
    const int lane = t & 31, warp = t >> 5;

    const float c0 = g_compat[b * NSEQ + t];
    const float c1 = g_compat[b * NSEQ + t + 1024];

    // block max (deterministic)
    float m = fmaxf(c0, c1);
    #pragma unroll
    for (int o = 16; o; o >>= 1) m = fmaxf(m, __shfl_xor_sync(~0u, m, o));
    if (lane == 0) redf[warp] = m;
    __syncthreads();
    float mx = redf[0];
    #pragma unroll
    for (int i = 1; i < 32; i++) mx = fmaxf(mx, redf[i]);

    // monotone key: flush-tie below boundary, order-preserving float bits above
    auto mkkey = [&](float c) -> unsigned {
        float d = c - mx;
        if (d < -87.33654785f) return 0u;        // tied (score flushed to 0)
        unsigned u = __float_as_uint(c);
        return (u & 0x80000000u) ? ~u : (u | 0x80000000u);
    };
    sk[t]        = mkkey(c0);  si[t]        = t;
    sk[t + 1024] = mkkey(c1);  si[t + 1024] = t + 1024;

    // bitonic full sort: key desc, index asc (total order)
    for (int k = 2; k <= NSEQ; k <<= 1) {
        for (int j = k >> 1; j > 0; j >>= 1) {
            __syncthreads();
            #pragma unroll
            for (int half = 0; half < 2; half++) {
                const int i = half * 1024 + t;
                const int ixj = i ^ j;
                if (ixj > i) {
                    const bool desc = ((i & k) == 0);
                    unsigned ki = sk[i], kj = sk[ixj];
                    int      ii = si[i], ij = si[ixj];
                    const bool jBeforeI = (kj > ki) || (kj == ki && ij < ii);
                    if (desc ? jBeforeI : !jBeforeI) {
                        sk[i] = kj; sk[ixj] = ki;
                        si[i] = ij; si[ixj] = ii;
                    }
                }
            }
        }
    }
    __syncthreads();
    if (t < NFOCUS) g_idx[b * NFOCUS + t] = si[t];
}

// ---------------- gather: out[b,r,:] = ve[b, idx[b,r], :] -------------------
__global__ void gather_k(const float* __restrict__ ve, float* __restrict__ out) {
    const int b = blockIdx.y, r = blockIdx.x;
    const int idx = g_idx[b * NFOCUS + r];
    const float4* src = (const float4*)(ve + ((size_t)b * NSEQ + idx) * HDIM);
    float4* dst = (float4*)(out + ((size_t)b * NFOCUS + r) * HDIM);
    dst[threadIdx.x] = src[threadIdx.x];
}

// ---------------- launch ----------------------------------------------------
extern "C" void kernel_launch(void* const* d_in, const int* in_sizes, int n_in,
                              void* d_out, int out_size) {
    const float* vs = (const float*)d_in[0];   // (64, 1, 512)
    const float* ve = (const float*)d_in[1];   // (64, 2048, 512)
    const float* Wq = (const float*)d_in[2];   // (512, 262144)
    const float* bq = (const float*)d_in[3];   // (262144,)
    const float* Wk = (const float*)d_in[4];   // (512, 262144)
    const float* bk = (const float*)d_in[5];   // (262144,)
    float* out = (float*)d_out;                // (64, 256, 512)

    gemm_xw<<<HH / 256, 256>>>(vs, Wq, bq);
    contract_q<<<dim3(8, BATCH), 512>>>(vs);
    reduce_q<<<BATCH, HDIM>>>();

    gemm_xw<<<HH / 256, 256>>>(vs, Wk, bk);
    contract_w<<<dim3(64, BATCH), 256>>>();

    compat_k<<<dim3(NSEQ / 8, BATCH), 256>>>(ve);
    topk_k<<<BATCH, 1024>>>();
    gather_k<<<dim3(NFOCUS, BATCH), 128>>>(ve, out);
}

// round 5
// speedup vs baseline: 1.0538x; 1.0538x over previous
#include <cuda_runtime.h>
#include <cuda_bf16.h>
#include <cstdint>

#define BATCH 64
#define HDIM 512
#define HH 262144      // HDIM*HDIM
#define NSEQ 2048
#define NFOCUS 256

// ---------------- scratch (static device globals; no runtime allocation) ----
__device__ float g_Y[(size_t)BATCH * HH];      // 64 MB (Yq then Yk)
__device__ float g_Qp[8 * BATCH * HDIM];
__device__ float g_Q[BATCH * HDIM];
__device__ float g_w[BATCH * HDIM];
__device__ float g_compat[BATCH * NSEQ];
__device__ int   g_idx[BATCH * NFOCUS];

// ======================= mma.sync helpers (HMMA path) =======================
__device__ __forceinline__ uint32_t smem_u32(const void* p) {
    uint32_t a;
    asm("{ .reg .u64 t; cvta.to.shared.u64 t, %1; cvt.u32.u64 %0, t; }"
        : "=r"(a) : "l"(p));
    return a;
}
__device__ __forceinline__ void ldsm4(uint32_t* r, uint32_t a) {
    asm volatile("ldmatrix.sync.aligned.m8n8.x4.shared.b16 {%0,%1,%2,%3}, [%4];"
                 : "=r"(r[0]), "=r"(r[1]), "=r"(r[2]), "=r"(r[3]) : "r"(a));
}
__device__ __forceinline__ void ldsm2(uint32_t* r, uint32_t a) {
    asm volatile("ldmatrix.sync.aligned.m8n8.x2.shared.b16 {%0,%1}, [%2];"
                 : "=r"(r[0]), "=r"(r[1]) : "r"(a));
}
__device__ __forceinline__ void mma16816(float* c, const uint32_t* a, const uint32_t* b) {
    asm volatile(
        "mma.sync.aligned.m16n8k16.row.col.f32.bf16.bf16.f32 "
        "{%0,%1,%2,%3}, {%4,%5,%6,%7}, {%8,%9}, {%0,%1,%2,%3};"
        : "+f"(c[0]), "+f"(c[1]), "+f"(c[2]), "+f"(c[3])
        : "r"(a[0]), "r"(a[1]), "r"(a[2]), "r"(a[3]), "r"(b[0]), "r"(b[1]));
}
__device__ __forceinline__ void split3(float x, uint16_t& s1, uint16_t& s2, uint16_t& s3) {
    __nv_bfloat16 b1 = __float2bfloat16_rn(x);
    float r1 = x - __bfloat162float(b1);
    __nv_bfloat16 b2 = __float2bfloat16_rn(r1);
    float r2 = r1 - __bfloat162float(b2);
    __nv_bfloat16 b3 = __float2bfloat16_rn(r2);
    s1 = __bfloat16_as_ushort(b1);
    s2 = __bfloat16_as_ushort(b2);
    s3 = __bfloat16_as_ushort(b3);
}

// ============ emulated-fp32 GEMM via 3-way bf16 split on mma.sync ============
// Y[b, n] = sum_k X[b,k] * W[k,n] + bias[n]
// TN layout: A = X[b][k] (row-major), B = W^T[n][k] (k contiguous) -> no .trans.
// 6 products (levels la+lb <= 2) -> dropped terms <= 2^-24.
#define KC 32                        // k per chunk
#define NCHUNK (HDIM / KC)           // 16
#define NTILE 256                    // n per CTA
#define ROWB 80                      // padded smem row bytes (64B data + 16B pad)
// smem layout (bytes from base):
//   Ws[buf][lvl] : NTILE rows x ROWB   -> 20480 per lvl, 61440 per buf
//   Xs[buf][lvl] : 64 rows x ROWB      ->  5120 per lvl, 15360 per buf
#define WS_OFF(buf, lvl) ((buf) * 61440u + (lvl) * 20480u)
#define XS_OFF(buf, lvl) (122880u + (buf) * 15360u + (lvl) * 5120u)
#define SMEM_BYTES 153600

__global__ __launch_bounds__(256, 1) void gemm_mma(
    const float* __restrict__ X, const float* __restrict__ W,
    const float* __restrict__ bias)
{
    extern __shared__ __align__(16) char smem_raw[];
    const uint32_t sb = smem_u32(smem_raw);
    const int tid = threadIdx.x;
    const int wid = tid >> 5, lane = tid & 31;
    const int n0 = blockIdx.x * NTILE;

    // warp work split: mpair -> batches [32*mpair, 32*mpair+32), noct -> 64 n's
    const int mpair = wid & 1;
    const int noct  = wid >> 1;

    float acc[2][8][4];
    #pragma unroll
    for (int m = 0; m < 2; m++)
        #pragma unroll
        for (int j = 0; j < 8; j++)
            #pragma unroll
            for (int q = 0; q < 4; q++) acc[m][j][q] = 0.f;

    // producer indices
    const int xb = tid >> 2, xq = tid & 3;        // X: batch row, k-quarter(8)
    float wreg[KC], xreg[8];

    // fragment smem addresses (constant parts)
    const uint32_t a_row_byte = (uint32_t)(32 * mpair + (lane & 15)) * ROWB + ((lane >> 4) << 4);
    const uint32_t b_row_byte = (uint32_t)(noct * 64 + (lane & 7)) * ROWB + (((lane >> 3) & 1) << 4);

    // ---- load chunk 0 ----
    #pragma unroll
    for (int j = 0; j < KC; j++) wreg[j] = W[(size_t)j * HH + n0 + tid];
    #pragma unroll
    for (int i = 0; i < 8; i++) xreg[i] = X[xb * HDIM + xq * 8 + i];

    // ---- store chunk 0 into buf 0 ----
    {
        uint32_t u1[16], u2[16], u3[16];
        #pragma unroll
        for (int p = 0; p < 16; p++) {
            uint16_t a1, a2, a3, c1, c2, c3;
            split3(wreg[2 * p], a1, a2, a3);
            split3(wreg[2 * p + 1], c1, c2, c3);
            u1[p] = (uint32_t)a1 | ((uint32_t)c1 << 16);
            u2[p] = (uint32_t)a2 | ((uint32_t)c2 << 16);
            u3[p] = (uint32_t)a3 | ((uint32_t)c3 << 16);
        }
        const uint32_t rb = (uint32_t)tid * ROWB;
        #pragma unroll
        for (int q = 0; q < 4; q++) {
            asm volatile("st.shared.v4.b32 [%0], {%1,%2,%3,%4};" ::
                "r"(sb + WS_OFF(0, 0) + rb + q * 16), "r"(u1[4*q]), "r"(u1[4*q+1]), "r"(u1[4*q+2]), "r"(u1[4*q+3]) : "memory");
            asm volatile("st.shared.v4.b32 [%0], {%1,%2,%3,%4};" ::
                "r"(sb + WS_OFF(0, 1) + rb + q * 16), "r"(u2[4*q]), "r"(u2[4*q+1]), "r"(u2[4*q+2]), "r"(u2[4*q+3]) : "memory");
            asm volatile("st.shared.v4.b32 [%0], {%1,%2,%3,%4};" ::
                "r"(sb + WS_OFF(0, 2) + rb + q * 16), "r"(u3[4*q]), "r"(u3[4*q+1]), "r"(u3[4*q+2]), "r"(u3[4*q+3]) : "memory");
        }
        uint32_t v1[4], v2[4], v3[4];
        #pragma unroll
        for (int p = 0; p < 4; p++) {
            uint16_t a1, a2, a3, c1, c2, c3;
            split3(xreg[2 * p], a1, a2, a3);
            split3(xreg[2 * p + 1], c1, c2, c3);
            v1[p] = (uint32_t)a1 | ((uint32_t)c1 << 16);
            v2[p] = (uint32_t)a2 | ((uint32_t)c2 << 16);
            v3[p] = (uint32_t)a3 | ((uint32_t)c3 << 16);
        }
        const uint32_t xrb = (uint32_t)xb * ROWB + xq * 16;
        asm volatile("st.shared.v4.b32 [%0], {%1,%2,%3,%4};" ::
            "r"(sb + XS_OFF(0, 0) + xrb), "r"(v1[0]), "r"(v1[1]), "r"(v1[2]), "r"(v1[3]) : "memory");
        asm volatile("st.shared.v4.b32 [%0], {%1,%2,%3,%4};" ::
            "r"(sb + XS_OFF(0, 1) + xrb), "r"(v2[0]), "r"(v2[1]), "r"(v2[2]), "r"(v2[3]) : "memory");
        asm volatile("st.shared.v4.b32 [%0], {%1,%2,%3,%4};" ::
            "r"(sb + XS_OFF(0, 2) + xrb), "r"(v3[0]), "r"(v3[1]), "r"(v3[2]), "r"(v3[3]) : "memory");
    }
    __syncthreads();

    for (int kc = 0; kc < NCHUNK; kc++) {
        const int cur = kc & 1, nxt = cur ^ 1;

        // prefetch next chunk (global -> regs), overlaps with mma below
        if (kc < NCHUNK - 1) {
            const int k0 = (kc + 1) * KC;
            #pragma unroll
            for (int j = 0; j < KC; j++) wreg[j] = W[(size_t)(k0 + j) * HH + n0 + tid];
            #pragma unroll
            for (int i = 0; i < 8; i++) xreg[i] = X[xb * HDIM + k0 + xq * 8 + i];
        }

        // ---- mma on current buffer: lb outer so B-frags are reused ----
        #pragma unroll
        for (int lb = 0; lb < 3; lb++) {
            #pragma unroll
            for (int ks = 0; ks < 2; ks++) {
                uint32_t bfr[8][2];
                #pragma unroll
                for (int j = 0; j < 8; j++)
                    ldsm2(bfr[j], sb + WS_OFF(cur, lb) + b_row_byte + (uint32_t)j * (8 * ROWB) + ks * 32);
                #pragma unroll
                for (int la = 0; la < 3; la++) {
                    if (la + lb > 2) break;
                    #pragma unroll
                    for (int m = 0; m < 2; m++) {
                        uint32_t af[4];
                        ldsm4(af, sb + XS_OFF(cur, la) + a_row_byte + (uint32_t)m * (16 * ROWB) + ks * 32);
                        #pragma unroll
                        for (int j = 0; j < 8; j++)
                            mma16816(acc[m][j], af, bfr[j]);
                    }
                }
            }
        }

        // ---- convert + store next chunk into other buffer ----
        if (kc < NCHUNK - 1) {
            uint32_t u1[16], u2[16], u3[16];
            #pragma unroll
            for (int p = 0; p < 16; p++) {
                uint16_t a1, a2, a3, c1, c2, c3;
                split3(wreg[2 * p], a1, a2, a3);
                split3(wreg[2 * p + 1], c1, c2, c3);
                u1[p] = (uint32_t)a1 | ((uint32_t)c1 << 16);
                u2[p] = (uint32_t)a2 | ((uint32_t)c2 << 16);
                u3[p] = (uint32_t)a3 | ((uint32_t)c3 << 16);
            }
            const uint32_t rb = (uint32_t)tid * ROWB;
            #pragma unroll
            for (int q = 0; q < 4; q++) {
                asm volatile("st.shared.v4.b32 [%0], {%1,%2,%3,%4};" ::
                    "r"(sb + WS_OFF(nxt, 0) + rb + q * 16), "r"(u1[4*q]), "r"(u1[4*q+1]), "r"(u1[4*q+2]), "r"(u1[4*q+3]) : "memory");
                asm volatile("st.shared.v4.b32 [%0], {%1,%2,%3,%4};" ::
                    "r"(sb + WS_OFF(nxt, 1) + rb + q * 16), "r"(u2[4*q]), "r"(u2[4*q+1]), "r"(u2[4*q+2]), "r"(u2[4*q+3]) : "memory");
                asm volatile("st.shared.v4.b32 [%0], {%1,%2,%3,%4};" ::
                    "r"(sb + WS_OFF(nxt, 2) + rb + q * 16), "r"(u3[4*q]), "r"(u3[4*q+1]), "r"(u3[4*q+2]), "r"(u3[4*q+3]) : "memory");
            }
            uint32_t v1[4], v2[4], v3[4];
            #pragma unroll
            for (int p = 0; p < 4; p++) {
                uint16_t a1, a2, a3, c1, c2, c3;
                split3(xreg[2 * p], a1, a2, a3);
                split3(xreg[2 * p + 1], c1, c2, c3);
                v1[p] = (uint32_t)a1 | ((uint32_t)c1 << 16);
                v2[p] = (uint32_t)a2 | ((uint32_t)c2 << 16);
                v3[p] = (uint32_t)a3 | ((uint32_t)c3 << 16);
            }
            const uint32_t xrb = (uint32_t)xb * ROWB + xq * 16;
            asm volatile("st.shared.v4.b32 [%0], {%1,%2,%3,%4};" ::
                "r"(sb + XS_OFF(nxt, 0) + xrb), "r"(v1[0]), "r"(v1[1]), "r"(v1[2]), "r"(v1[3]) : "memory");
            asm volatile("st.shared.v4.b32 [%0], {%1,%2,%3,%4};" ::
                "r"(sb + XS_OFF(nxt, 1) + xrb), "r"(v2[0]), "r"(v2[1]), "r"(v2[2]), "r"(v2[3]) : "memory");
            asm volatile("st.shared.v4.b32 [%0], {%1,%2,%3,%4};" ::
                "r"(sb + XS_OFF(nxt, 2) + xrb), "r"(v3[0]), "r"(v3[1]), "r"(v3[2]), "r"(v3[3]) : "memory");
        }
        __syncthreads();
    }

    // ---- epilogue: C fragment -> g_Y + bias ----
    // d0,d1: (b = 32*mpair + 16*m + lane>>2, n = j*8 + (lane&3)*2); d2,d3: b+8
    const int ncol = n0 + noct * 64 + (lane & 3) * 2;
    #pragma unroll
    for (int m = 0; m < 2; m++) {
        const int brow = 32 * mpair + 16 * m + (lane >> 2);
        #pragma unroll
        for (int j = 0; j < 8; j++) {
            const int n = ncol + j * 8;
            const float2 bz = *(const float2*)&bias[n];
            float2 o0 = make_float2(acc[m][j][0] + bz.x, acc[m][j][1] + bz.y);
            float2 o1 = make_float2(acc[m][j][2] + bz.x, acc[m][j][3] + bz.y);
            *(float2*)&g_Y[(size_t)brow * HH + n]       = o0;
            *(float2*)&g_Y[(size_t)(brow + 8) * HH + n] = o1;
        }
    }
}

// ---------------- Qpart[s,b,k] = sum_{h in slice s} x[b,h] * Y[b, h*H + k] --
__global__ void contract_q(const float* __restrict__ X) {
    const int b = blockIdx.y, s = blockIdx.x;
    const int k = threadIdx.x;  // 512
    __shared__ float xs[64];
    if (k < 64) xs[k] = X[b * HDIM + s * 64 + k];
    __syncthreads();
    const float* Yb = g_Y + (size_t)b * HH + (size_t)s * 64 * HDIM + k;
    float a0 = 0.f, a1 = 0.f, a2 = 0.f, a3 = 0.f;
    #pragma unroll
    for (int hh = 0; hh < 64; hh += 4) {
        a0 = fmaf(xs[hh + 0], Yb[(hh + 0) * HDIM], a0);
        a1 = fmaf(xs[hh + 1], Yb[(hh + 1) * HDIM], a1);
        a2 = fmaf(xs[hh + 2], Yb[(hh + 2) * HDIM], a2);
        a3 = fmaf(xs[hh + 3], Yb[(hh + 3) * HDIM], a3);
    }
    g_Qp[(s * BATCH + b) * HDIM + k] = (a0 + a1) + (a2 + a3);
}

__global__ void reduce_q() {
    const int b = blockIdx.x, k = threadIdx.x;
    float v = 0.f;
    #pragma unroll
    for (int s = 0; s < 8; s++) v += g_Qp[(s * BATCH + b) * HDIM + k];
    g_Q[b * HDIM + k] = v;
}

// ---------------- w[b,h] = < Y[b, h*H : h*H+H] , Q[b,:] > -------------------
__global__ void contract_w() {
    const int b = blockIdx.y;
    const int warp = threadIdx.x >> 5, lane = threadIdx.x & 31;
    const int h = blockIdx.x * 8 + warp;
    __shared__ float qs[HDIM];
    for (int i = threadIdx.x; i < HDIM; i += 256) qs[i] = g_Q[b * HDIM + i];
    __syncthreads();
    const float* Yb = g_Y + (size_t)b * HH + (size_t)h * HDIM;
    float acc = 0.f;
    #pragma unroll
    for (int s2 = 0; s2 < 4; s2++) {
        const int i4 = lane + s2 * 32;
        float4 y = *(const float4*)&Yb[i4 * 4];
        float4 q = *(const float4*)&qs[i4 * 4];
        acc += y.x * q.x + y.y * q.y + y.z * q.z + y.w * q.w;
    }
    #pragma unroll
    for (int off = 16; off; off >>= 1) acc += __shfl_xor_sync(~0u, acc, off);
    if (lane == 0) g_w[b * HDIM + h] = acc;
}

// ---------------- compat[b,n] = norm * < ve[b,n,:], w[b,:] > ----------------
__global__ void compat_k(const float* __restrict__ ve) {
    const int b = blockIdx.y;
    const int warp = threadIdx.x >> 5, lane = threadIdx.x & 31;
    const int n = blockIdx.x * 8 + warp;
    __shared__ float ws[HDIM];
    for (int i = threadIdx.x; i < HDIM; i += 256) ws[i] = g_w[b * HDIM + i];
    __syncthreads();
    const float* v = ve + ((size_t)b * NSEQ + n) * HDIM;
    float acc = 0.f;
    #pragma unroll
    for (int s2 = 0; s2 < 4; s2++) {
        const int i4 = lane + s2 * 32;
        float4 y = *(const float4*)&v[i4 * 4];
        float4 q = *(const float4*)&ws[i4 * 4];
        acc += y.x * q.x + y.y * q.y + y.z * q.z + y.w * q.w;
    }
    #pragma unroll
    for (int off = 16; off; off >>= 1) acc += __shfl_xor_sync(~0u, acc, off);
    if (lane == 0) g_compat[b * NSEQ + n] = acc * 0.04419417382415922f;
}

// ---------------- per-batch ranking with fp32-exp flush boundary ------------
__global__ __launch_bounds__(1024) void topk_k() {
    __shared__ unsigned sk[NSEQ];
    __shared__ int      si[NSEQ];
    __shared__ float    redf[32];
    const int b = blockIdx.x, t = threadIdx.x;
    const int lane = t & 31, warp = t >> 5;

    const float c0 = g_compat[b * NSEQ + t];
    const float c1 = g_compat[b * NSEQ + t + 1024];

    float m = fmaxf(c0, c1);
    #pragma unroll
    for (int o = 16; o; o >>= 1) m = fmaxf(m, __shfl_xor_sync(~0u, m, o));
    if (lane == 0) redf[warp] = m;
    __syncthreads();
    float mx = redf[0];
    #pragma unroll
    for (int i = 1; i < 32; i++) mx = fmaxf(mx, redf[i]);

    auto mkkey = [&](float c) -> unsigned {
        float d = c - mx;
        if (d < -87.33654785f) return 0u;
        unsigned u = __float_as_uint(c);
        return (u & 0x80000000u) ? ~u : (u | 0x80000000u);
    };
    sk[t]        = mkkey(c0);  si[t]        = t;
    sk[t + 1024] = mkkey(c1);  si[t + 1024] = t + 1024;

    for (int k = 2; k <= NSEQ; k <<= 1) {
        for (int j = k >> 1; j > 0; j >>= 1) {
            __syncthreads();
            #pragma unroll
            for (int half = 0; half < 2; half++) {
                const int i = half * 1024 + t;
                const int ixj = i ^ j;
                if (ixj > i) {
                    const bool desc = ((i & k) == 0);
                    unsigned ki = sk[i], kj = sk[ixj];
                    int      ii = si[i], ij = si[ixj];
                    const bool jBeforeI = (kj > ki) || (kj == ki && ij < ii);
                    if (desc ? jBeforeI : !jBeforeI) {
                        sk[i] = kj; sk[ixj] = ki;
                        si[i] = ij; si[ixj] = ii;
                    }
                }
            }
        }
    }
    __syncthreads();
    if (t < NFOCUS) g_idx[b * NFOCUS + t] = si[t];
}

// ---------------- gather: out[b,r,:] = ve[b, idx[b,r], :] -------------------
__global__ void gather_k(const float* __restrict__ ve, float* __restrict__ out) {
    const int b = blockIdx.y, r = blockIdx.x;
    const int idx = g_idx[b * NFOCUS + r];
    const float4* src = (const float4*)(ve + ((size_t)b * NSEQ + idx) * HDIM);
    float4* dst = (float4*)(out + ((size_t)b * NFOCUS + r) * HDIM);
    dst[threadIdx.x] = src[threadIdx.x];
}

// ---------------- launch ----------------------------------------------------
extern "C" void kernel_launch(void* const* d_in, const int* in_sizes, int n_in,
                              void* d_out, int out_size) {
    const float* vs = (const float*)d_in[0];   // (64, 1, 512)
    const float* ve = (const float*)d_in[1];   // (64, 2048, 512)
    const float* Wq = (const float*)d_in[2];   // (512, 262144)
    const float* bq = (const float*)d_in[3];   // (262144,)
    const float* Wk = (const float*)d_in[4];   // (512, 262144)
    const float* bk = (const float*)d_in[5];   // (262144,)
    float* out = (float*)d_out;                // (64, 256, 512)

    cudaFuncSetAttribute(gemm_mma, cudaFuncAttributeMaxDynamicSharedMemorySize, SMEM_BYTES);

    gemm_mma<<<HH / NTILE, 256, SMEM_BYTES>>>(vs, Wq, bq);
    contract_q<<<dim3(8, BATCH), 512>>>(vs);
    reduce_q<<<BATCH, HDIM>>>();

    gemm_mma<<<HH / NTILE, 256, SMEM_BYTES>>>(vs, Wk, bk);
    contract_w<<<dim3(64, BATCH), 256>>>();

    compat_k<<<dim3(NSEQ / 8, BATCH), 256>>>(ve);
    topk_k<<<BATCH, 1024>>>();
    gather_k<<<dim3(NFOCUS, BATCH), 128>>>(ve, out);
}

// round 6
// speedup vs baseline: 1.0958x; 1.0399x over previous
#include <cuda_runtime.h>
#include <cuda_fp16.h>
#include <cstdint>

#define BATCH 64
#define HDIM 512
#define HH 262144      // HDIM*HDIM
#define NSEQ 2048
#define NFOCUS 256

// ---------------- scratch (static device globals; no runtime allocation) ----
__device__ float g_Y[(size_t)BATCH * HH];      // 64 MB (Yq then Yk)
__device__ float g_Qp[8 * BATCH * HDIM];
__device__ float g_Q[BATCH * HDIM];
__device__ float g_w[BATCH * HDIM];
__device__ float g_compat[BATCH * NSEQ];
__device__ int   g_idx[BATCH * NFOCUS];

// ======================= mma.sync helpers (HMMA path) =======================
__device__ __forceinline__ uint32_t smem_u32(const void* p) {
    uint32_t a;
    asm("{ .reg .u64 t; cvta.to.shared.u64 t, %1; cvt.u32.u64 %0, t; }"
        : "=r"(a) : "l"(p));
    return a;
}
__device__ __forceinline__ void ldsm4(uint32_t* r, uint32_t a) {
    asm volatile("ldmatrix.sync.aligned.m8n8.x4.shared.b16 {%0,%1,%2,%3}, [%4];"
                 : "=r"(r[0]), "=r"(r[1]), "=r"(r[2]), "=r"(r[3]) : "r"(a));
}
__device__ __forceinline__ void ldsm2(uint32_t* r, uint32_t a) {
    asm volatile("ldmatrix.sync.aligned.m8n8.x2.shared.b16 {%0,%1}, [%2];"
                 : "=r"(r[0]), "=r"(r[1]) : "r"(a));
}
__device__ __forceinline__ void mma16816(float* c, const uint32_t* a, const uint32_t* b) {
    asm volatile(
        "mma.sync.aligned.m16n8k16.row.col.f32.f16.f16.f32 "
        "{%0,%1,%2,%3}, {%4,%5,%6,%7}, {%8,%9}, {%0,%1,%2,%3};"
        : "+f"(c[0]), "+f"(c[1]), "+f"(c[2]), "+f"(c[3])
        : "r"(a[0]), "r"(a[1]), "r"(a[2]), "r"(a[3]), "r"(b[0]), "r"(b[1]));
}
// x ~= h1 + 2^-11 * h2  (h2 holds the residue scaled by 2^11 -> normal range)
__device__ __forceinline__ void split2h(float x, uint16_t& h1, uint16_t& h2) {
    __half a = __float2half_rn(x);
    float r = (x - __half2float(a)) * 2048.0f;
    __half b = __float2half_rn(r);
    h1 = __half_as_ushort(a);
    h2 = __half_as_ushort(b);
}

// ========= emulated-fp32 GEMM via 2-way fp16 split (3 HMMA products) ========
// Y[b,n] = sum_k X[b,k] W[k,n] + bias[n]
// acc_lo += x1 w1 ; acc_hi += x1 w2' + x2' w1 ; Y = lo + hi/2048 + bias
#define KC 32                        // k per chunk
#define NCHUNK (HDIM / KC)           // 16
#define NTILE 128                    // n per CTA
#define THREADS 512
#define ROWB 80                      // padded smem row bytes (64B data + 16B pad)
// smem: Ws[buf][lvl]: 128 x 80 = 10240 ; Xs[buf][lvl]: 64 x 80 = 5120
#define WS_OFF(buf, lvl) ((buf) * 20480u + (lvl) * 10240u)
#define XS_OFF(buf, lvl) (40960u + (buf) * 10240u + (lvl) * 5120u)
#define SMEM_BYTES 61440

__global__ __launch_bounds__(THREADS, 1) void gemm_mma(
    const float* __restrict__ X, const float* __restrict__ W,
    const float* __restrict__ bias)
{
    extern __shared__ __align__(16) char smem_raw[];
    const uint32_t sb = smem_u32(smem_raw);
    const int tid = threadIdx.x;
    const int wid = tid >> 5, lane = tid & 31;
    const int n0 = blockIdx.x * NTILE;

    // warp tile: 32 batches (mpair) x 16 n (noct)
    const int mpair = wid & 1;
    const int noct  = wid >> 1;          // 0..7

    float lo[2][2][4], hi[2][2][4];
    #pragma unroll
    for (int m = 0; m < 2; m++)
        #pragma unroll
        for (int j = 0; j < 2; j++)
            #pragma unroll
            for (int q = 0; q < 4; q++) { lo[m][j][q] = 0.f; hi[m][j][q] = 0.f; }

    // producers
    const int wn = tid & 127, wkh = tid >> 7;     // W: n col, k-octet (0..3)
    const int xb = tid >> 3, xq = tid & 7;        // X: batch row, k-quad
    float wreg[8], xreg[4];

    // fragment smem base offsets
    const uint32_t a_row = (uint32_t)(32 * mpair + (lane & 15)) * ROWB + ((lane >> 4) << 4);
    const uint32_t b_row = (uint32_t)(noct * 16 + (lane & 7)) * ROWB + (((lane >> 3) & 1) << 4);

    // ---- load + convert + store chunk 0 into buf 0 ----
    #pragma unroll
    for (int j = 0; j < 8; j++) wreg[j] = W[(size_t)(wkh * 8 + j) * HH + n0 + wn];
    {
        float4 v = *(const float4*)&X[xb * HDIM + xq * 4];
        xreg[0] = v.x; xreg[1] = v.y; xreg[2] = v.z; xreg[3] = v.w;
    }
    {
        uint32_t u1[4], u2[4];
        #pragma unroll
        for (int p = 0; p < 4; p++) {
            uint16_t a1, a2, c1, c2;
            split2h(wreg[2 * p], a1, a2);
            split2h(wreg[2 * p + 1], c1, c2);
            u1[p] = (uint32_t)a1 | ((uint32_t)c1 << 16);
            u2[p] = (uint32_t)a2 | ((uint32_t)c2 << 16);
        }
        const uint32_t rb = (uint32_t)wn * ROWB + wkh * 16;
        asm volatile("st.shared.v4.b32 [%0], {%1,%2,%3,%4};" ::
            "r"(sb + WS_OFF(0, 0) + rb), "r"(u1[0]), "r"(u1[1]), "r"(u1[2]), "r"(u1[3]) : "memory");
        asm volatile("st.shared.v4.b32 [%0], {%1,%2,%3,%4};" ::
            "r"(sb + WS_OFF(0, 1) + rb), "r"(u2[0]), "r"(u2[1]), "r"(u2[2]), "r"(u2[3]) : "memory");
        uint32_t v1[2], v2[2];
        #pragma unroll
        for (int p = 0; p < 2; p++) {
            uint16_t a1, a2, c1, c2;
            split2h(xreg[2 * p], a1, a2);
            split2h(xreg[2 * p + 1], c1, c2);
            v1[p] = (uint32_t)a1 | ((uint32_t)c1 << 16);
            v2[p] = (uint32_t)a2 | ((uint32_t)c2 << 16);
        }
        const uint32_t xrb = (uint32_t)xb * ROWB + xq * 8;
        asm volatile("st.shared.v2.b32 [%0], {%1,%2};" ::
            "r"(sb + XS_OFF(0, 0) + xrb), "r"(v1[0]), "r"(v1[1]) : "memory");
        asm volatile("st.shared.v2.b32 [%0], {%1,%2};" ::
            "r"(sb + XS_OFF(0, 1) + xrb), "r"(v2[0]), "r"(v2[1]) : "memory");
    }
    __syncthreads();

    for (int kc = 0; kc < NCHUNK; kc++) {
        const int cur = kc & 1, nxt = cur ^ 1;

        // prefetch next chunk into regs (overlaps the mma phase)
        if (kc < NCHUNK - 1) {
            const int k0 = (kc + 1) * KC;
            #pragma unroll
            for (int j = 0; j < 8; j++) wreg[j] = W[(size_t)(k0 + wkh * 8 + j) * HH + n0 + wn];
            float4 v = *(const float4*)&X[xb * HDIM + k0 + xq * 4];
            xreg[0] = v.x; xreg[1] = v.y; xreg[2] = v.z; xreg[3] = v.w;
        }

        // ---- mma on current buffer ----
        #pragma unroll
        for (int ks = 0; ks < 2; ks++) {
            uint32_t b1[2][2], b2[2][2], a1[2][4], a2[2][4];
            #pragma unroll
            for (int j = 0; j < 2; j++) {
                ldsm2(b1[j], sb + WS_OFF(cur, 0) + b_row + (uint32_t)j * (8 * ROWB) + ks * 32);
                ldsm2(b2[j], sb + WS_OFF(cur, 1) + b_row + (uint32_t)j * (8 * ROWB) + ks * 32);
            }
            #pragma unroll
            for (int m = 0; m < 2; m++) {
                ldsm4(a1[m], sb + XS_OFF(cur, 0) + a_row + (uint32_t)m * (16 * ROWB) + ks * 32);
                ldsm4(a2[m], sb + XS_OFF(cur, 1) + a_row + (uint32_t)m * (16 * ROWB) + ks * 32);
            }
            #pragma unroll
            for (int m = 0; m < 2; m++)
                #pragma unroll
                for (int j = 0; j < 2; j++) mma16816(lo[m][j], a1[m], b1[j]);
            #pragma unroll
            for (int m = 0; m < 2; m++)
                #pragma unroll
                for (int j = 0; j < 2; j++) mma16816(hi[m][j], a1[m], b2[j]);
            #pragma unroll
            for (int m = 0; m < 2; m++)
                #pragma unroll
                for (int j = 0; j < 2; j++) mma16816(hi[m][j], a2[m], b1[j]);
        }

        // ---- convert + store next chunk into other buffer ----
        if (kc < NCHUNK - 1) {
            uint32_t u1[4], u2[4];
            #pragma unroll
            for (int p = 0; p < 4; p++) {
                uint16_t a1v, a2v, c1v, c2v;
                split2h(wreg[2 * p], a1v, a2v);
                split2h(wreg[2 * p + 1], c1v, c2v);
                u1[p] = (uint32_t)a1v | ((uint32_t)c1v << 16);
                u2[p] = (uint32_t)a2v | ((uint32_t)c2v << 16);
            }
            const uint32_t rb = (uint32_t)wn * ROWB + wkh * 16;
            asm volatile("st.shared.v4.b32 [%0], {%1,%2,%3,%4};" ::
                "r"(sb + WS_OFF(nxt, 0) + rb), "r"(u1[0]), "r"(u1[1]), "r"(u1[2]), "r"(u1[3]) : "memory");
            asm volatile("st.shared.v4.b32 [%0], {%1,%2,%3,%4};" ::
                "r"(sb + WS_OFF(nxt, 1) + rb), "r"(u2[0]), "r"(u2[1]), "r"(u2[2]), "r"(u2[3]) : "memory");
            uint32_t v1[2], v2[2];
            #pragma unroll
            for (int p = 0; p < 2; p++) {
                uint16_t a1v, a2v, c1v, c2v;
                split2h(xreg[2 * p], a1v, a2v);
                split2h(xreg[2 * p + 1], c1v, c2v);
                v1[p] = (uint32_t)a1v | ((uint32_t)c1v << 16);
                v2[p] = (uint32_t)a2v | ((uint32_t)c2v << 16);
            }
            const uint32_t xrb = (uint32_t)xb * ROWB + xq * 8;
            asm volatile("st.shared.v2.b32 [%0], {%1,%2};" ::
                "r"(sb + XS_OFF(nxt, 0) + xrb), "r"(v1[0]), "r"(v1[1]) : "memory");
            asm volatile("st.shared.v2.b32 [%0], {%1,%2};" ::
                "r"(sb + XS_OFF(nxt, 1) + xrb), "r"(v2[0]), "r"(v2[1]) : "memory");
        }
        __syncthreads();
    }

    // ---- epilogue: Y = lo + hi/2048 + bias ----
    const float s = 1.0f / 2048.0f;
    const int ncol = n0 + noct * 16 + (lane & 3) * 2;
    #pragma unroll
    for (int m = 0; m < 2; m++) {
        const int brow = 32 * mpair + 16 * m + (lane >> 2);
        #pragma unroll
        for (int j = 0; j < 2; j++) {
            const int n = ncol + j * 8;
            const float2 bz = *(const float2*)&bias[n];
            float2 o0 = make_float2(fmaf(hi[m][j][0], s, lo[m][j][0]) + bz.x,
                                    fmaf(hi[m][j][1], s, lo[m][j][1]) + bz.y);
            float2 o1 = make_float2(fmaf(hi[m][j][2], s, lo[m][j][2]) + bz.x,
                                    fmaf(hi[m][j][3], s, lo[m][j][3]) + bz.y);
            *(float2*)&g_Y[(size_t)brow * HH + n]       = o0;
            *(float2*)&g_Y[(size_t)(brow + 8) * HH + n] = o1;
        }
    }
}

// ---------------- Qpart[s,b,k] = sum_{h in slice s} x[b,h] * Y[b, h*H + k] --
__global__ void contract_q(const float* __restrict__ X) {
    const int b = blockIdx.y, s = blockIdx.x;
    const int k = threadIdx.x;  // 512
    __shared__ float xs[64];
    if (k < 64) xs[k] = X[b * HDIM + s * 64 + k];
    __syncthreads();
    const float* Yb = g_Y + (size_t)b * HH + (size_t)s * 64 * HDIM + k;
    float a0 = 0.f, a1 = 0.f, a2 = 0.f, a3 = 0.f;
    #pragma unroll
    for (int hh = 0; hh < 64; hh += 4) {
        a0 = fmaf(xs[hh + 0], Yb[(hh + 0) * HDIM], a0);
        a1 = fmaf(xs[hh + 1], Yb[(hh + 1) * HDIM], a1);
        a2 = fmaf(xs[hh + 2], Yb[(hh + 2) * HDIM], a2);
        a3 = fmaf(xs[hh + 3], Yb[(hh + 3) * HDIM], a3);
    }
    g_Qp[(s * BATCH + b) * HDIM + k] = (a0 + a1) + (a2 + a3);
}

__global__ void reduce_q() {
    const int b = blockIdx.x, k = threadIdx.x;
    float v = 0.f;
    #pragma unroll
    for (int s = 0; s < 8; s++) v += g_Qp[(s * BATCH + b) * HDIM + k];
    g_Q[b * HDIM + k] = v;
}

// ---------------- w[b,h] = < Y[b, h*H : h*H+H] , Q[b,:] > -------------------
__global__ void contract_w() {
    const int b = blockIdx.y;
    const int warp = threadIdx.x >> 5, lane = threadIdx.x & 31;
    const int h = blockIdx.x * 8 + warp;
    __shared__ float qs[HDIM];
    for (int i = threadIdx.x; i < HDIM; i += 256) qs[i] = g_Q[b * HDIM + i];
    __syncthreads();
    const float* Yb = g_Y + (size_t)b * HH + (size_t)h * HDIM;
    float acc = 0.f;
    #pragma unroll
    for (int s2 = 0; s2 < 4; s2++) {
        const int i4 = lane + s2 * 32;
        float4 y = *(const float4*)&Yb[i4 * 4];
        float4 q = *(const float4*)&qs[i4 * 4];
        acc += y.x * q.x + y.y * q.y + y.z * q.z + y.w * q.w;
    }
    #pragma unroll
    for (int off = 16; off; off >>= 1) acc += __shfl_xor_sync(~0u, acc, off);
    if (lane == 0) g_w[b * HDIM + h] = acc;
}

// ---------------- compat[b,n] = norm * < ve[b,n,:], w[b,:] > ----------------
__global__ void compat_k(const float* __restrict__ ve) {
    const int b = blockIdx.y;
    const int warp = threadIdx.x >> 5, lane = threadIdx.x & 31;
    const int n = blockIdx.x * 8 + warp;
    __shared__ float ws[HDIM];
    for (int i = threadIdx.x; i < HDIM; i += 256) ws[i] = g_w[b * HDIM + i];
    __syncthreads();
    const float* v = ve + ((size_t)b * NSEQ + n) * HDIM;
    float acc = 0.f;
    #pragma unroll
    for (int s2 = 0; s2 < 4; s2++) {
        const int i4 = lane + s2 * 32;
        float4 y = *(const float4*)&v[i4 * 4];
        float4 q = *(const float4*)&ws[i4 * 4];
        acc += y.x * q.x + y.y * q.y + y.z * q.z + y.w * q.w;
    }
    #pragma unroll
    for (int off = 16; off; off >>= 1) acc += __shfl_xor_sync(~0u, acc, off);
    if (lane == 0) g_compat[b * NSEQ + n] = acc * 0.04419417382415922f;
}

// ---------------- per-batch ranking with fp32-exp flush boundary ------------
__global__ __launch_bounds__(1024) void topk_k() {
    __shared__ unsigned sk[NSEQ];
    __shared__ int      si[NSEQ];
    __shared__ float    redf[32];
    const int b = blockIdx.x, t = threadIdx.x;
    const int lane = t & 31, warp = t >> 5;

    const float c0 = g_compat[b * NSEQ + t];
    const float c1 = g_compat[b * NSEQ + t + 1024];

    float m = fmaxf(c0, c1);
    #pragma unroll
    for (int o = 16; o; o >>= 1) m = fmaxf(m, __shfl_xor_sync(~0u, m, o));
    if (lane == 0) redf[warp] = m;
    __syncthreads();
    float mx = redf[0];
    #pragma unroll
    for (int i = 1; i < 32; i++) mx = fmaxf(mx, redf[i]);

    auto mkkey = [&](float c) -> unsigned {
        float d = c - mx;
        if (d < -87.33654785f) return 0u;
        unsigned u = __float_as_uint(c);
        return (u & 0x80000000u) ? ~u : (u | 0x80000000u);
    };
    sk[t]        = mkkey(c0);  si[t]        = t;
    sk[t + 1024] = mkkey(c1);  si[t + 1024] = t + 1024;

    for (int k = 2; k <= NSEQ; k <<= 1) {
        for (int j = k >> 1; j > 0; j >>= 1) {
            __syncthreads();
            #pragma unroll
            for (int half = 0; half < 2; half++) {
                const int i = half * 1024 + t;
                const int ixj = i ^ j;
                if (ixj > i) {
                    const bool desc = ((i & k) == 0);
                    unsigned ki = sk[i], kj = sk[ixj];
                    int      ii = si[i], ij = si[ixj];
                    const bool jBeforeI = (kj > ki) || (kj == ki && ij < ii);
                    if (desc ? jBeforeI : !jBeforeI) {
                        sk[i] = kj; sk[ixj] = ki;
                        si[i] = ij; si[ixj] = ii;
                    }
                }
            }
        }
    }
    __syncthreads();
    if (t < NFOCUS) g_idx[b * NFOCUS + t] = si[t];
}

// ---------------- gather: out[b,r,:] = ve[b, idx[b,r], :] -------------------
__global__ void gather_k(const float* __restrict__ ve, float* __restrict__ out) {
    const int b = blockIdx.y, r = blockIdx.x;
    const int idx = g_idx[b * NFOCUS + r];
    const float4* src = (const float4*)(ve + ((size_t)b * NSEQ + idx) * HDIM);
    float4* dst = (float4*)(out + ((size_t)b * NFOCUS + r) * HDIM);
    dst[threadIdx.x] = src[threadIdx.x];
}

// ---------------- launch ----------------------------------------------------
extern "C" void kernel_launch(void* const* d_in, const int* in_sizes, int n_in,
                              void* d_out, int out_size) {
    const float* vs = (const float*)d_in[0];   // (64, 1, 512)
    const float* ve = (const float*)d_in[1];   // (64, 2048, 512)
    const float* Wq = (const float*)d_in[2];   // (512, 262144)
    const float* bq = (const float*)d_in[3];   // (262144,)
    const float* Wk = (const float*)d_in[4];   // (512, 262144)
    const float* bk = (const float*)d_in[5];   // (262144,)
    float* out = (float*)d_out;                // (64, 256, 512)

    cudaFuncSetAttribute(gemm_mma, cudaFuncAttributeMaxDynamicSharedMemorySize, SMEM_BYTES);

    gemm_mma<<<HH / NTILE, THREADS, SMEM_BYTES>>>(vs, Wq, bq);
    contract_q<<<dim3(8, BATCH), 512>>>(vs);
    reduce_q<<<BATCH, HDIM>>>();

    gemm_mma<<<HH / NTILE, THREADS, SMEM_BYTES>>>(vs, Wk, bk);
    contract_w<<<dim3(64, BATCH), 256>>>();

    compat_k<<<dim3(NSEQ / 8, BATCH), 256>>>(ve);
    topk_k<<<BATCH, 1024>>>();
    gather_k<<<dim3(NFOCUS, BATCH), 128>>>(ve, out);
}

// round 7
// speedup vs baseline: 1.2964x; 1.1830x over previous
#include <cuda_runtime.h>
#include <cuda_fp16.h>
#include <cstdint>

#define BATCH 64
#define HDIM 512
#define HH 262144      // HDIM*HDIM
#define NSEQ 2048
#define NFOCUS 256

// ---------------- scratch (static device globals; no runtime allocation) ----
__device__ float g_Y[(size_t)BATCH * HH];      // 64 MB (Yq then Yk)
__device__ float g_Qp[8 * BATCH * HDIM];
__device__ float g_Q[BATCH * HDIM];
__device__ float g_w[BATCH * HDIM];
__device__ float g_compat[BATCH * NSEQ];
__device__ int   g_idx[BATCH * NFOCUS];

// ======================= mma.sync helpers (HMMA path) =======================
__device__ __forceinline__ uint32_t smem_u32(const void* p) {
    uint32_t a;
    asm("{ .reg .u64 t; cvta.to.shared.u64 t, %1; cvt.u32.u64 %0, t; }"
        : "=r"(a) : "l"(p));
    return a;
}
__device__ __forceinline__ void ldsm4(uint32_t* r, uint32_t a) {
    asm volatile("ldmatrix.sync.aligned.m8n8.x4.shared.b16 {%0,%1,%2,%3}, [%4];"
                 : "=r"(r[0]), "=r"(r[1]), "=r"(r[2]), "=r"(r[3]) : "r"(a));
}
__device__ __forceinline__ void ldsm2(uint32_t* r, uint32_t a) {
    asm volatile("ldmatrix.sync.aligned.m8n8.x2.shared.b16 {%0,%1}, [%2];"
                 : "=r"(r[0]), "=r"(r[1]) : "r"(a));
}
__device__ __forceinline__ void mma16816(float* c, const uint32_t* a, const uint32_t* b) {
    asm volatile(
        "mma.sync.aligned.m16n8k16.row.col.f32.f16.f16.f32 "
        "{%0,%1,%2,%3}, {%4,%5,%6,%7}, {%8,%9}, {%0,%1,%2,%3};"
        : "+f"(c[0]), "+f"(c[1]), "+f"(c[2]), "+f"(c[3])
        : "r"(a[0]), "r"(a[1]), "r"(a[2]), "r"(a[3]), "r"(b[0]), "r"(b[1]));
}
// x ~= h1 + 2^-11 * h2  (h2 holds the residue scaled by 2^11 -> normal range)
__device__ __forceinline__ void split2h(float x, uint16_t& h1, uint16_t& h2) {
    __half a = __float2half_rn(x);
    float r = (x - __half2float(a)) * 2048.0f;
    __half b = __float2half_rn(r);
    h1 = __half_as_ushort(a);
    h2 = __half_as_ushort(b);
}
__device__ __forceinline__ void cp16(uint32_t dst, const void* src) {
    asm volatile("cp.async.cg.shared.global [%0], [%1], 16;"
                 :: "r"(dst), "l"(src) : "memory");
}
#define CP_COMMIT() asm volatile("cp.async.commit_group;" ::: "memory")

// ========= emulated-fp32 GEMM via 2-way fp16 split (3 HMMA products) ========
// Y[b,n] = sum_k X[b,k] W[k,n] + bias[n]
// cp.async 4-stage pipeline: raw fp32 chunks stream into smem; convert reads
// smem (not LDG regs), writes fp16 split buffers; mma consumes prior buffer.
#define KC 32                        // k per chunk
#define NCHUNK (HDIM / KC)           // 16
#define NTILE 128                    // n per CTA
#define THREADS 512
#define NSTAGE 4
#define ROWB 80                      // padded fp16 smem row bytes (64B + 16 pad)
// smem byte offsets:
#define RAWW_OFF(st)      ((st) * 16384u)                     // 32k x 128n x 4B
#define RAWX_OFF(st)      (65536u + (st) * 8192u)             // 64b x 32k x 4B
#define WS_OFF(buf, lvl)  (98304u + (buf) * 20480u + (lvl) * 10240u)
#define XS_OFF(buf, lvl)  (139264u + (buf) * 10240u + (lvl) * 5120u)
#define SMEM_BYTES 159744

__global__ __launch_bounds__(THREADS, 1) void gemm_mma(
    const float* __restrict__ X, const float* __restrict__ W,
    const float* __restrict__ bias)
{
    extern __shared__ __align__(16) char smem_raw[];
    const uint32_t sb = smem_u32(smem_raw);
    const int tid = threadIdx.x;
    const int wid = tid >> 5, lane = tid & 31;
    const int n0 = blockIdx.x * NTILE;

    // warp tile: 32 batches (mpair) x 16 n (noct)
    const int mpair = wid & 1;
    const int noct  = wid >> 1;          // 0..7

    float lo[2][2][4], hi[2][2][4];
    #pragma unroll
    for (int m = 0; m < 2; m++)
        #pragma unroll
        for (int j = 0; j < 2; j++)
            #pragma unroll
            for (int q = 0; q < 4; q++) { lo[m][j][q] = 0.f; hi[m][j][q] = 0.f; }

    // converter mappings
    const int wn = tid & 127, wkh = tid >> 7;     // W: n col, k-octet (0..3)
    const int xb = tid >> 3, xq = tid & 7;        // X: batch row, k-quad

    // fragment smem base offsets
    const uint32_t a_row = (uint32_t)(32 * mpair + (lane & 15)) * ROWB + ((lane >> 4) << 4);
    const uint32_t b_row = (uint32_t)(noct * 16 + (lane & 7)) * ROWB + (((lane >> 3) & 1) << 4);

    // producer segment mapping for cp.async (W: 1024 16B-segs, 2 per thread)
    const int segk0 = tid >> 5, segn = tid & 31;  // seg t: k=segk0, n-off=segn*16B

    // ---- helpers as macros over locals ----
    #define ISSUE_STAGE(stg, chunk) do {                                         \
        const uint32_t wdst = sb + RAWW_OFF(stg);                                \
        const float* wsrc = W + (size_t)((chunk) * KC) * HH + n0;                \
        cp16(wdst + (uint32_t)segk0 * 512u + (uint32_t)segn * 16u,               \
             wsrc + (size_t)segk0 * HH + segn * 4);                              \
        cp16(wdst + (uint32_t)(segk0 + 16) * 512u + (uint32_t)segn * 16u,        \
             wsrc + (size_t)(segk0 + 16) * HH + segn * 4);                       \
        cp16(sb + RAWX_OFF(stg) + (uint32_t)xb * 128u + (uint32_t)xq * 16u,      \
             X + (size_t)xb * HDIM + (chunk) * KC + xq * 4);                     \
        CP_COMMIT();                                                             \
    } while (0)

    #define CONVERT_STAGE(stg, buf) do {                                         \
        const char* rw = smem_raw + RAWW_OFF(stg);                               \
        float wv[8];                                                             \
        _Pragma("unroll")                                                        \
        for (int j = 0; j < 8; j++)                                              \
            wv[j] = *(const float*)(rw + (uint32_t)(wkh * 8 + j) * 512u + (uint32_t)wn * 4u); \
        uint32_t u1[4], u2[4];                                                   \
        _Pragma("unroll")                                                        \
        for (int p = 0; p < 4; p++) {                                            \
            uint16_t a1v, a2v, c1v, c2v;                                         \
            split2h(wv[2 * p], a1v, a2v);                                        \
            split2h(wv[2 * p + 1], c1v, c2v);                                    \
            u1[p] = (uint32_t)a1v | ((uint32_t)c1v << 16);                       \
            u2[p] = (uint32_t)a2v | ((uint32_t)c2v << 16);                       \
        }                                                                        \
        const uint32_t rb = (uint32_t)wn * ROWB + wkh * 16;                      \
        asm volatile("st.shared.v4.b32 [%0], {%1,%2,%3,%4};" ::                  \
            "r"(sb + WS_OFF(buf, 0) + rb), "r"(u1[0]), "r"(u1[1]), "r"(u1[2]), "r"(u1[3]) : "memory"); \
        asm volatile("st.shared.v4.b32 [%0], {%1,%2,%3,%4};" ::                  \
            "r"(sb + WS_OFF(buf, 1) + rb), "r"(u2[0]), "r"(u2[1]), "r"(u2[2]), "r"(u2[3]) : "memory"); \
        float4 xv = *(const float4*)(smem_raw + RAWX_OFF(stg) + (uint32_t)xb * 128u + (uint32_t)xq * 16u); \
        uint32_t v1[2], v2[2];                                                   \
        {                                                                        \
            uint16_t a1v, a2v, c1v, c2v;                                         \
            split2h(xv.x, a1v, a2v); split2h(xv.y, c1v, c2v);                    \
            v1[0] = (uint32_t)a1v | ((uint32_t)c1v << 16);                       \
            v2[0] = (uint32_t)a2v | ((uint32_t)c2v << 16);                       \
            split2h(xv.z, a1v, a2v); split2h(xv.w, c1v, c2v);                    \
            v1[1] = (uint32_t)a1v | ((uint32_t)c1v << 16);                       \
            v2[1] = (uint32_t)a2v | ((uint32_t)c2v << 16);                       \
        }                                                                        \
        const uint32_t xrb = (uint32_t)xb * ROWB + xq * 8;                       \
        asm volatile("st.shared.v2.b32 [%0], {%1,%2};" ::                        \
            "r"(sb + XS_OFF(buf, 0) + xrb), "r"(v1[0]), "r"(v1[1]) : "memory");  \
        asm volatile("st.shared.v2.b32 [%0], {%1,%2};" ::                        \
            "r"(sb + XS_OFF(buf, 1) + xrb), "r"(v2[0]), "r"(v2[1]) : "memory");  \
    } while (0)

    // ---- prologue: stages 0..2 in flight; convert chunk 0 ----
    ISSUE_STAGE(0, 0);
    ISSUE_STAGE(1, 1);
    ISSUE_STAGE(2, 2);
    asm volatile("cp.async.wait_group 2;" ::: "memory");
    __syncthreads();
    CONVERT_STAGE(0, 0);

    for (int kc = 0; kc < NCHUNK; kc++) {
        const int cur = kc & 1;

        if (kc + 3 < NCHUNK) ISSUE_STAGE((kc + 3) & 3, kc + 3);

        if (kc + 1 < NCHUNK) {
            if (kc < NCHUNK - 3)      asm volatile("cp.async.wait_group 2;" ::: "memory");
            else if (kc == NCHUNK - 3) asm volatile("cp.async.wait_group 1;" ::: "memory");
            else                       asm volatile("cp.async.wait_group 0;" ::: "memory");
        }
        __syncthreads();

        if (kc + 1 < NCHUNK) CONVERT_STAGE((kc + 1) & 3, (kc + 1) & 1);

        // ---- mma on current fp16 buffer ----
        #pragma unroll
        for (int ks = 0; ks < 2; ks++) {
            uint32_t b1[2][2], b2[2][2], a1[2][4], a2[2][4];
            #pragma unroll
            for (int j = 0; j < 2; j++) {
                ldsm2(b1[j], sb + WS_OFF(cur, 0) + b_row + (uint32_t)j * (8 * ROWB) + ks * 32);
                ldsm2(b2[j], sb + WS_OFF(cur, 1) + b_row + (uint32_t)j * (8 * ROWB) + ks * 32);
            }
            #pragma unroll
            for (int m = 0; m < 2; m++) {
                ldsm4(a1[m], sb + XS_OFF(cur, 0) + a_row + (uint32_t)m * (16 * ROWB) + ks * 32);
                ldsm4(a2[m], sb + XS_OFF(cur, 1) + a_row + (uint32_t)m * (16 * ROWB) + ks * 32);
            }
            #pragma unroll
            for (int m = 0; m < 2; m++)
                #pragma unroll
                for (int j = 0; j < 2; j++) mma16816(lo[m][j], a1[m], b1[j]);
            #pragma unroll
            for (int m = 0; m < 2; m++)
                #pragma unroll
                for (int j = 0; j < 2; j++) mma16816(hi[m][j], a1[m], b2[j]);
            #pragma unroll
            for (int m = 0; m < 2; m++)
                #pragma unroll
                for (int j = 0; j < 2; j++) mma16816(hi[m][j], a2[m], b1[j]);
        }
    }

    // ---- epilogue: Y = lo + hi/2048 + bias ----
    const float s = 1.0f / 2048.0f;
    const int ncol = n0 + noct * 16 + (lane & 3) * 2;
    #pragma unroll
    for (int m = 0; m < 2; m++) {
        const int brow = 32 * mpair + 16 * m + (lane >> 2);
        #pragma unroll
        for (int j = 0; j < 2; j++) {
            const int n = ncol + j * 8;
            const float2 bz = *(const float2*)&bias[n];
            float2 o0 = make_float2(fmaf(hi[m][j][0], s, lo[m][j][0]) + bz.x,
                                    fmaf(hi[m][j][1], s, lo[m][j][1]) + bz.y);
            float2 o1 = make_float2(fmaf(hi[m][j][2], s, lo[m][j][2]) + bz.x,
                                    fmaf(hi[m][j][3], s, lo[m][j][3]) + bz.y);
            *(float2*)&g_Y[(size_t)brow * HH + n]       = o0;
            *(float2*)&g_Y[(size_t)(brow + 8) * HH + n] = o1;
        }
    }
    #undef ISSUE_STAGE
    #undef CONVERT_STAGE
}

// ---------------- Qpart[s,b,k] = sum_{h in slice s} x[b,h] * Y[b, h*H + k] --
__global__ void contract_q(const float* __restrict__ X) {
    const int b = blockIdx.y, s = blockIdx.x;
    const int k = threadIdx.x;  // 512
    __shared__ float xs[64];
    if (k < 64) xs[k] = X[b * HDIM + s * 64 + k];
    __syncthreads();
    const float* Yb = g_Y + (size_t)b * HH + (size_t)s * 64 * HDIM + k;
    float a0 = 0.f, a1 = 0.f, a2 = 0.f, a3 = 0.f;
    #pragma unroll
    for (int hh = 0; hh < 64; hh += 4) {
        a0 = fmaf(xs[hh + 0], Yb[(hh + 0) * HDIM], a0);
        a1 = fmaf(xs[hh + 1], Yb[(hh + 1) * HDIM], a1);
        a2 = fmaf(xs[hh + 2], Yb[(hh + 2) * HDIM], a2);
        a3 = fmaf(xs[hh + 3], Yb[(hh + 3) * HDIM], a3);
    }
    g_Qp[(s * BATCH + b) * HDIM + k] = (a0 + a1) + (a2 + a3);
}

__global__ void reduce_q() {
    const int b = blockIdx.x, k = threadIdx.x;
    float v = 0.f;
    #pragma unroll
    for (int s = 0; s < 8; s++) v += g_Qp[(s * BATCH + b) * HDIM + k];
    g_Q[b * HDIM + k] = v;
}

// ---------------- w[b,h] = < Y[b, h*H : h*H+H] , Q[b,:] > -------------------
__global__ void contract_w() {
    const int b = blockIdx.y;
    const int warp = threadIdx.x >> 5, lane = threadIdx.x & 31;
    const int h = blockIdx.x * 8 + warp;
    __shared__ float qs[HDIM];
    for (int i = threadIdx.x; i < HDIM; i += 256) qs[i] = g_Q[b * HDIM + i];
    __syncthreads();
    const float* Yb = g_Y + (size_t)b * HH + (size_t)h * HDIM;
    float acc = 0.f;
    #pragma unroll
    for (int s2 = 0; s2 < 4; s2++) {
        const int i4 = lane + s2 * 32;
        float4 y = *(const float4*)&Yb[i4 * 4];
        float4 q = *(const float4*)&qs[i4 * 4];
        acc += y.x * q.x + y.y * q.y + y.z * q.z + y.w * q.w;
    }
    #pragma unroll
    for (int off = 16; off; off >>= 1) acc += __shfl_xor_sync(~0u, acc, off);
    if (lane == 0) g_w[b * HDIM + h] = acc;
}

// ---------------- compat[b,n] = norm * < ve[b,n,:], w[b,:] > ----------------
__global__ void compat_k(const float* __restrict__ ve) {
    const int b = blockIdx.y;
    const int warp = threadIdx.x >> 5, lane = threadIdx.x & 31;
    const int n = blockIdx.x * 8 + warp;
    __shared__ float ws[HDIM];
    for (int i = threadIdx.x; i < HDIM; i += 256) ws[i] = g_w[b * HDIM + i];
    __syncthreads();
    const float* v = ve + ((size_t)b * NSEQ + n) * HDIM;
    float acc = 0.f;
    #pragma unroll
    for (int s2 = 0; s2 < 4; s2++) {
        const int i4 = lane + s2 * 32;
        float4 y = *(const float4*)&v[i4 * 4];
        float4 q = *(const float4*)&ws[i4 * 4];
        acc += y.x * q.x + y.y * q.y + y.z * q.z + y.w * q.w;
    }
    #pragma unroll
    for (int off = 16; off; off >>= 1) acc += __shfl_xor_sync(~0u, acc, off);
    if (lane == 0) g_compat[b * NSEQ + n] = acc * 0.04419417382415922f;
}

// ---------------- per-batch ranking with fp32-exp flush boundary ------------
__global__ __launch_bounds__(1024) void topk_k() {
    __shared__ unsigned sk[NSEQ];
    __shared__ int      si[NSEQ];
    __shared__ float    redf[32];
    const int b = blockIdx.x, t = threadIdx.x;
    const int lane = t & 31, warp = t >> 5;

    const float c0 = g_compat[b * NSEQ + t];
    const float c1 = g_compat[b * NSEQ + t + 1024];

    float m = fmaxf(c0, c1);
    #pragma unroll
    for (int o = 16; o; o >>= 1) m = fmaxf(m, __shfl_xor_sync(~0u, m, o));
    if (lane == 0) redf[warp] = m;
    __syncthreads();
    float mx = redf[0];
    #pragma unroll
    for (int i = 1; i < 32; i++) mx = fmaxf(mx, redf[i]);

    auto mkkey = [&](float c) -> unsigned {
        float d = c - mx;
        if (d < -87.33654785f) return 0u;
        unsigned u = __float_as_uint(c);
        return (u & 0x80000000u) ? ~u : (u | 0x80000000u);
    };
    sk[t]        = mkkey(c0);  si[t]        = t;
    sk[t + 1024] = mkkey(c1);  si[t + 1024] = t + 1024;

    for (int k = 2; k <= NSEQ; k <<= 1) {
        for (int j = k >> 1; j > 0; j >>= 1) {
            __syncthreads();
            #pragma unroll
            for (int half = 0; half < 2; half++) {
                const int i = half * 1024 + t;
                const int ixj = i ^ j;
                if (ixj > i) {
                    const bool desc = ((i & k) == 0);
                    unsigned ki = sk[i], kj = sk[ixj];
                    int      ii = si[i], ij = si[ixj];
                    const bool jBeforeI = (kj > ki) || (kj == ki && ij < ii);
                    if (desc ? jBeforeI : !jBeforeI) {
                        sk[i] = kj; sk[ixj] = ki;
                        si[i] = ij; si[ixj] = ii;
                    }
                }
            }
        }
    }
    __syncthreads();
    if (t < NFOCUS) g_idx[b * NFOCUS + t] = si[t];
}

// ---------------- gather: out[b,r,:] = ve[b, idx[b,r], :] -------------------
__global__ void gather_k(const float* __restrict__ ve, float* __restrict__ out) {
    const int b = blockIdx.y, r = blockIdx.x;
    const int idx = g_idx[b * NFOCUS + r];
    const float4* src = (const float4*)(ve + ((size_t)b * NSEQ + idx) * HDIM);
    float4* dst = (float4*)(out + ((size_t)b * NFOCUS + r) * HDIM);
    dst[threadIdx.x] = src[threadIdx.x];
}

// ---------------- launch ----------------------------------------------------
extern "C" void kernel_launch(void* const* d_in, const int* in_sizes, int n_in,
                              void* d_out, int out_size) {
    const float* vs = (const float*)d_in[0];   // (64, 1, 512)
    const float* ve = (const float*)d_in[1];   // (64, 2048, 512)
    const float* Wq = (const float*)d_in[2];   // (512, 262144)
    const float* bq = (const float*)d_in[3];   // (262144,)
    const float* Wk = (const float*)d_in[4];   // (512, 262144)
    const float* bk = (const float*)d_in[5];   // (262144,)
    float* out = (float*)d_out;                // (64, 256, 512)

    cudaFuncSetAttribute(gemm_mma, cudaFuncAttributeMaxDynamicSharedMemorySize, SMEM_BYTES);

    gemm_mma<<<HH / NTILE, THREADS, SMEM_BYTES>>>(vs, Wq, bq);
    contract_q<<<dim3(8, BATCH), 512>>>(vs);
    reduce_q<<<BATCH, HDIM>>>();

    gemm_mma<<<HH / NTILE, THREADS, SMEM_BYTES>>>(vs, Wk, bk);
    contract_w<<<dim3(64, BATCH), 256>>>();

    compat_k<<<dim3(NSEQ / 8, BATCH), 256>>>(ve);
    topk_k<<<BATCH, 1024>>>();
    gather_k<<<dim3(NFOCUS, BATCH), 128>>>(ve, out);
}